// round 16
// baseline (speedup 1.0000x reference)
#include <cuda_runtime.h>
#include <cstdint>

// ---------------- problem constants ----------------
#define B_    256
#define P_    512
#define D_    16
#define DIN   17          // D+1 (particle dims + weight feature)
#define H_    256
#define G3    768         // 3*H
#define ACT   8
#define NCRIT 2
#define HID_  256
#define INM   265         // H + A + 1

// ---------------- GRU cluster kernel config ----------------
#define CS    4           // cluster size
#define JC    64          // hidden columns owned per CTA (H/CS)
#define BC    8           // batch rows per cluster
#define NCL   32          // clusters (NCL*BC == B_)
#define TPB   512         // 1 batch row per thread: tid = jl*8 + tg

#define WP    260         // padded pitch (floats) for weight & h rows

#define OFF_W   0                         // [3][JC][WP]  gate weights (k contiguous)
#define OFF_WI  (3*JC*WP)                 // [3][DIN][JC] input weights (jl contiguous)
#define OFF_BI  (OFF_WI + 3*DIN*JC)       // [3][JC] input biases
#define OFF_BN  (OFF_BI + 3*JC)           // [JC] bn
#define OFF_H   (OFF_BN + JC)             // [2][BC][WP] double-buffered hidden state
#define OFF_X   (OFF_H + 2*BC*WP)         // [2][BC][20] double-buffered x features
#define SMEM_FLOATS (OFF_X + 2*BC*20)     // 57920 floats
#define SMEM_BYTES  (SMEM_FLOATS*4)       // 231680 B  (<= 232448 opt-in)

__device__ float g_enc[B_*H_];            // GRU final hidden, handed to MLP kernel

// ---------------- helpers ----------------
__device__ __forceinline__ void fma2(unsigned long long &acc,
                                     unsigned long long a,
                                     unsigned long long b) {
    asm volatile("fma.rn.f32x2 %0, %1, %2, %0;" : "+l"(acc) : "l"(a), "l"(b));
}

__device__ __forceinline__ float f2red(unsigned long long a, unsigned long long b) {
    unsigned long long c;
    asm("add.rn.f32x2 %0, %1, %2;" : "=l"(c) : "l"(a), "l"(b));
    float lo, hi;
    asm("mov.b64 {%0, %1}, %2;" : "=f"(lo), "=f"(hi) : "l"(c));
    return lo + hi;
}

__device__ __forceinline__ float sigf(float x) {
    return 1.0f / (1.0f + __expf(-x));
}
__device__ __forceinline__ float tanh_f(float x) {
    return 1.0f - 2.0f / (__expf(2.0f * x) + 1.0f);
}

__device__ __forceinline__ void st_remote(uint32_t laddr, uint32_t rank, float v) {
    uint32_t ra;
    asm volatile("mapa.shared::cluster.u32 %0, %1, %2;" : "=r"(ra) : "r"(laddr), "r"(rank));
    asm volatile("st.shared::cluster.f32 [%0], %1;" :: "r"(ra), "f"(v));
}

#define CL_ARRIVE() asm volatile("barrier.cluster.arrive.aligned;" ::: "memory")
#define CL_WAIT()   asm volatile("barrier.cluster.wait.aligned;"   ::: "memory")

// =====================================================================
// Kernel 1: GRU recurrence.
// Cluster of 4 CTAs; CTA `rank` owns gate columns [64*rank, 64*rank+64)
// for 8 batch rows; weights SMEM-resident; h exchanged via DSMEM each step.
// 512 threads: tid = jl*8 + tg -> thread handles column jl, batch row tg.
// Barrier split: arrive at step end, wait hidden under next step's x-prefetch
// + input-gate GEMM (which never touch h).
// =====================================================================
__global__ void __launch_bounds__(TPB, 1) __cluster_dims__(CS, 1, 1)
gru_kernel(const float* __restrict__ particles,  // [B,P,D]
           const float* __restrict__ pw,         // [B,P]
           const float* __restrict__ Wi,         // [DIN, 3H]
           const float* __restrict__ bi,         // [3H]
           const float* __restrict__ Whrz,       // [H, 2H]
           const float* __restrict__ Whn,        // [H, H]
           const float* __restrict__ bn)         // [H]
{
    extern __shared__ float sm[];
    const int tid   = threadIdx.x;
    const int rank  = blockIdx.x & (CS - 1);
    const int cid   = blockIdx.x >> 2;
    const int jbase = rank * JC;
    const int cbase = cid * BC;

    // ---- load owned weight columns (one-time) ----
    for (int idx = tid; idx < JC * H_; idx += TPB) {
        int k = idx >> 6, jl = idx & 63;
        sm[OFF_W + jl * WP + k]            = Whrz[k * (2*H_) + jbase + jl];        // r
        sm[OFF_W + (JC + jl) * WP + k]     = Whrz[k * (2*H_) + H_ + jbase + jl];   // z
        sm[OFF_W + (2*JC + jl) * WP + k]   = Whn [k * H_ + jbase + jl];            // n
    }
    for (int idx = tid; idx < 3 * DIN * JC; idx += TPB) {
        int jl = idx & 63; int rem = idx >> 6;
        int g = rem / DIN, d = rem % DIN;
        sm[OFF_WI + (g * DIN + d) * JC + jl] = Wi[d * G3 + g * H_ + jbase + jl];
    }
    if (tid < 3 * JC) {
        int g = tid >> 6, jl = tid & 63;
        sm[OFF_BI + tid] = bi[g * H_ + jbase + jl];
    }
    if (tid < JC) sm[OFF_BN + tid] = bn[jbase + tid];
    for (int idx = tid; idx < BC * WP; idx += TPB) sm[OFF_H + idx] = 0.0f;  // h0 = 0
    if (tid < BC * DIN) {   // stage x for p = 0
        int bb = tid / DIN, d = tid % DIN;
        int gb = cbase + bb;
        sm[OFF_X + bb * 20 + d] = (d < D_) ? particles[gb * (P_ * D_) + d]
                                           : pw[gb * P_];
    }
    __syncthreads();
    CL_ARRIVE(); CL_WAIT();

    const int jl = tid >> 3, tg = tid & 7;
    const int wR = OFF_W + jl * WP;
    const int wZ = OFF_W + (JC + jl) * WP;
    const int wN = OFF_W + (2*JC + jl) * WP;
    const uint32_t smem_base = (uint32_t)__cvta_generic_to_shared(sm);

    const float bir = sm[OFF_BI + jl];
    const float biz = sm[OFF_BI + JC + jl];
    const float bin = sm[OFF_BI + 2*JC + jl];
    const float bnv = sm[OFF_BN + jl];

    for (int p = 0; p < P_; ++p) {
        const int cur = p & 1, nxt = cur ^ 1;

        // 1. prefetch x for step p+1 into registers (hidden under wait+k-loop)
        float xpre = 0.0f; int pb = 0, pd = 0;
        if (p + 1 < P_ && tid < BC * DIN) {
            pb = tid / DIN; pd = tid % DIN;
            int gb = cbase + pb;
            xpre = (pd < D_) ? particles[gb * (P_ * D_) + (p + 1) * D_ + pd]
                             : pw[gb * P_ + (p + 1)];
        }

        // 2. input-gate contributions: gi = x @ Wi + bi (no dependence on h)
        float gr = bir, gz = biz, gn = bin;
        const float* xc = &sm[OFF_X + (cur * BC + tg) * 20];
        #pragma unroll
        for (int d = 0; d < DIN; ++d) {
            float xv = xc[d];
            gr += xv * sm[OFF_WI + d * JC + jl];
            gz += xv * sm[OFF_WI + (DIN + d) * JC + jl];
            gn += xv * sm[OFF_WI + (2*DIN + d) * JC + jl];
        }

        // 3. wait for previous step's h scatter (overlapped with 1+2)
        if (p) CL_WAIT();

        // 4. recurrent dots over k with packed f32x2 FMA
        unsigned long long arA = 0, azA = 0, anA = 0;
        unsigned long long arB = 0, azB = 0, anB = 0;
        const int hoff = OFF_H + (cur * BC + tg) * WP;
        #pragma unroll 4
        for (int k = 0; k < H_; k += 4) {
            ulonglong2 vr = *reinterpret_cast<const ulonglong2*>(&sm[wR + k]);
            ulonglong2 vz = *reinterpret_cast<const ulonglong2*>(&sm[wZ + k]);
            ulonglong2 vn = *reinterpret_cast<const ulonglong2*>(&sm[wN + k]);
            ulonglong2 ha = *reinterpret_cast<const ulonglong2*>(&sm[hoff + k]);
            fma2(arA, ha.x, vr.x); fma2(arB, ha.y, vr.y);
            fma2(azA, ha.x, vz.x); fma2(azB, ha.y, vz.y);
            fma2(anA, ha.x, vn.x); fma2(anB, ha.y, vn.y);
        }

        // 5. gates / new hidden
        float r = sigf(gr + f2red(arA, arB));
        float z = sigf(gz + f2red(azA, azB));
        float n = tanh_f(gn + r * (f2red(anA, anB) + bnv));
        float hold = sm[hoff + jbase + jl];
        float hnew = n + z * (hold - n);

        // scatter owned element to all CTAs' next h buffer
        const int hdst = OFF_H + (nxt * BC + tg) * WP + jbase + jl;
        sm[hdst] = hnew;                                  // local
        uint32_t la = smem_base + (uint32_t)(hdst * 4);
        #pragma unroll
        for (int r2 = 0; r2 < CS; ++r2)
            if (r2 != rank) st_remote(la, (uint32_t)r2, hnew);

        // 6. stash prefetched x into next buffer (local)
        if (p + 1 < P_ && tid < BC * DIN)
            sm[OFF_X + (nxt * BC + pb) * 20 + pd] = xpre;

        // 7+8. order local stores for local readers, then release to cluster
        __syncthreads();
        CL_ARRIVE();
    }

    CL_WAIT();   // consume final arrives; h final lives in buffer 0

    g_enc[(cbase + tg) * H_ + jbase + jl] = sm[OFF_H + tg * WP + jbase + jl];
}

// =====================================================================
// Kernel 2: twin-critic MLP, BB=4 batch rows per block to amortize the
// weight stream 4x. grid (C, B/BB) = (2, 64), 256 threads (t = unit).
// =====================================================================
#define BB 4

__global__ void __launch_bounds__(256)
mlp_kernel(const float* __restrict__ actions,   // [B, A]
           const float* __restrict__ timev,     // [B]
           const float* __restrict__ W1,        // [C, INM, HID]
           const float* __restrict__ b1,        // [C, HID]
           const float* __restrict__ W2,        // [C, HID, HID]
           const float* __restrict__ b2,        // [C, HID]
           const float* __restrict__ W3,        // [C, HID, 1]
           const float* __restrict__ b3,        // [C, 1]
           const int*   __restrict__ nts,       // scalar
           float*       __restrict__ out)       // [B, C]
{
    __shared__ float hid[BB][INM];
    __shared__ float h1s[BB][HID_];
    __shared__ float red[BB][8];

    const int c = blockIdx.x, b0 = blockIdx.y * BB, t = threadIdx.x;
    const float tinv = 1.0f / (float)nts[0];

    for (int idx = t; idx < BB * INM; idx += 256) {
        int bb = idx / INM, i = idx - bb * INM;
        int b = b0 + bb;
        float v;
        if (i < H_)            v = g_enc[b * H_ + i];
        else if (i < H_ + ACT) v = actions[b * ACT + (i - H_)];
        else                   v = timev[b] * tinv;
        hid[bb][i] = v;
    }
    __syncthreads();

    // layer 1
    float bb1 = b1[c * HID_ + t];
    float a0 = bb1, a1 = bb1, a2 = bb1, a3 = bb1;
    const float* w1p = W1 + (size_t)c * INM * HID_ + t;
    #pragma unroll 5
    for (int i = 0; i < INM; ++i) {
        float w = w1p[(size_t)i * HID_];
        a0 += hid[0][i] * w; a1 += hid[1][i] * w;
        a2 += hid[2][i] * w; a3 += hid[3][i] * w;
    }
    h1s[0][t] = fmaxf(a0, 0.0f); h1s[1][t] = fmaxf(a1, 0.0f);
    h1s[2][t] = fmaxf(a2, 0.0f); h1s[3][t] = fmaxf(a3, 0.0f);
    __syncthreads();

    // layer 2
    float bb2 = b2[c * HID_ + t];
    a0 = bb2; a1 = bb2; a2 = bb2; a3 = bb2;
    const float* w2p = W2 + (size_t)c * HID_ * HID_ + t;
    #pragma unroll 8
    for (int i = 0; i < HID_; ++i) {
        float w = w2p[(size_t)i * HID_];
        a0 += h1s[0][i] * w; a1 += h1s[1][i] * w;
        a2 += h1s[2][i] * w; a3 += h1s[3][i] * w;
    }

    // layer 3 + reduction
    float w3v = W3[c * HID_ + t];
    float v0 = fmaxf(a0, 0.0f) * w3v;
    float v1 = fmaxf(a1, 0.0f) * w3v;
    float v2 = fmaxf(a2, 0.0f) * w3v;
    float v3 = fmaxf(a3, 0.0f) * w3v;
    #pragma unroll
    for (int o = 16; o > 0; o >>= 1) {
        v0 += __shfl_xor_sync(0xffffffffu, v0, o);
        v1 += __shfl_xor_sync(0xffffffffu, v1, o);
        v2 += __shfl_xor_sync(0xffffffffu, v2, o);
        v3 += __shfl_xor_sync(0xffffffffu, v3, o);
    }
    if ((t & 31) == 0) {
        int w = t >> 5;
        red[0][w] = v0; red[1][w] = v1; red[2][w] = v2; red[3][w] = v3;
    }
    __syncthreads();
    if (t < BB) {
        float s = b3[c];
        #pragma unroll
        for (int w = 0; w < 8; ++w) s += red[t][w];
        out[(b0 + t) * NCRIT + c] = s;
    }
}

// =====================================================================
extern "C" void kernel_launch(void* const* d_in, const int* in_sizes, int n_in,
                              void* d_out, int out_size)
{
    const float* particles = (const float*)d_in[0];
    const float* pw        = (const float*)d_in[1];
    const float* actions   = (const float*)d_in[2];
    const float* timev     = (const float*)d_in[3];
    const float* Wi        = (const float*)d_in[4];
    const float* bi        = (const float*)d_in[5];
    const float* Whrz      = (const float*)d_in[6];
    const float* Whn       = (const float*)d_in[7];
    const float* bn        = (const float*)d_in[8];
    const float* W1        = (const float*)d_in[9];
    const float* b1        = (const float*)d_in[10];
    const float* W2        = (const float*)d_in[11];
    const float* b2        = (const float*)d_in[12];
    const float* W3        = (const float*)d_in[13];
    const float* b3        = (const float*)d_in[14];
    const int*   nts       = (const int*)d_in[15];

    cudaFuncSetAttribute(gru_kernel,
                         cudaFuncAttributeMaxDynamicSharedMemorySize, SMEM_BYTES);

    gru_kernel<<<NCL * CS, TPB, SMEM_BYTES>>>(particles, pw, Wi, bi, Whrz, Whn, bn);

    dim3 g2(NCRIT, B_ / BB);
    mlp_kernel<<<g2, 256>>>(actions, timev, W1, b1, W2, b2, W3, b3, nts,
                            (float*)d_out);
}

// round 17
// speedup vs baseline: 1.0021x; 1.0021x over previous
#include <cuda_runtime.h>
#include <cstdint>

// ---------------- problem constants ----------------
#define B_    256
#define P_    512
#define D_    16
#define DIN   17          // D+1 (particle dims + weight feature)
#define H_    256
#define G3    768         // 3*H
#define ACT   8
#define NCRIT 2
#define HID_  256
#define INM   265         // H + A + 1

// ---------------- GRU cluster kernel config ----------------
#define CS    4           // cluster size
#define JC    64          // hidden columns owned per CTA (H/CS)
#define BC    8           // batch rows per cluster
#define NCL   32          // clusters (NCL*BC == B_)
#define TPB   512         // 1 batch row per thread: tid = jl*8 + tg

#define WP    260         // padded pitch (floats) for weight & h rows

#define OFF_W   0                         // [3][JC][WP]  gate weights (k contiguous)
#define OFF_WI  (3*JC*WP)                 // [3][DIN][JC] input weights (jl contiguous)
#define OFF_BI  (OFF_WI + 3*DIN*JC)       // [3][JC] input biases
#define OFF_BN  (OFF_BI + 3*JC)           // [JC] bn
#define OFF_H   (OFF_BN + JC)             // [2][BC][WP] double-buffered hidden state
#define OFF_X   (OFF_H + 2*BC*WP)         // [2][BC][20] double-buffered x features
#define SMEM_FLOATS (OFF_X + 2*BC*20)     // 57920 floats
#define SMEM_BYTES  (SMEM_FLOATS*4)       // 231680 B  (<= 232448 opt-in)

__device__ float g_enc[B_*H_];            // GRU final hidden, handed to MLP kernel

// ---------------- helpers ----------------
__device__ __forceinline__ void fma2(unsigned long long &acc,
                                     unsigned long long a,
                                     unsigned long long b) {
    asm volatile("fma.rn.f32x2 %0, %1, %2, %0;" : "+l"(acc) : "l"(a), "l"(b));
}

__device__ __forceinline__ float f2red(unsigned long long a, unsigned long long b) {
    unsigned long long c;
    asm("add.rn.f32x2 %0, %1, %2;" : "=l"(c) : "l"(a), "l"(b));
    float lo, hi;
    asm("mov.b64 {%0, %1}, %2;" : "=f"(lo), "=f"(hi) : "l"(c));
    return lo + hi;
}

__device__ __forceinline__ float sigf(float x) {
    return 1.0f / (1.0f + __expf(-x));
}
__device__ __forceinline__ float tanh_f(float x) {
    return 1.0f - 2.0f / (__expf(2.0f * x) + 1.0f);
}

__device__ __forceinline__ void st_remote(uint32_t laddr, uint32_t rank, float v) {
    uint32_t ra;
    asm volatile("mapa.shared::cluster.u32 %0, %1, %2;" : "=r"(ra) : "r"(laddr), "r"(rank));
    asm volatile("st.shared::cluster.f32 [%0], %1;" :: "r"(ra), "f"(v));
}

#define CL_ARRIVE() asm volatile("barrier.cluster.arrive.aligned;" ::: "memory")
#define CL_WAIT()   asm volatile("barrier.cluster.wait.aligned;"   ::: "memory")

// =====================================================================
// Kernel 1: GRU recurrence.
// Cluster of 4 CTAs; CTA `rank` owns gate columns [64*rank, 64*rank+64)
// for 8 batch rows; weights SMEM-resident; h exchanged via DSMEM each step.
// 512 threads: tid = jl*8 + tg -> thread handles column jl, batch row tg.
// Barrier split: arrive at step end, wait hidden under next step's x-prefetch
// + input-gate GEMM (which never touch h).
// =====================================================================
__global__ void __launch_bounds__(TPB, 1) __cluster_dims__(CS, 1, 1)
gru_kernel(const float* __restrict__ particles,  // [B,P,D]
           const float* __restrict__ pw,         // [B,P]
           const float* __restrict__ Wi,         // [DIN, 3H]
           const float* __restrict__ bi,         // [3H]
           const float* __restrict__ Whrz,       // [H, 2H]
           const float* __restrict__ Whn,        // [H, H]
           const float* __restrict__ bn)         // [H]
{
    extern __shared__ float sm[];
    const int tid   = threadIdx.x;
    const int rank  = blockIdx.x & (CS - 1);
    const int cid   = blockIdx.x >> 2;
    const int jbase = rank * JC;
    const int cbase = cid * BC;

    // ---- load owned weight columns (one-time) ----
    for (int idx = tid; idx < JC * H_; idx += TPB) {
        int k = idx >> 6, jl = idx & 63;
        sm[OFF_W + jl * WP + k]            = Whrz[k * (2*H_) + jbase + jl];        // r
        sm[OFF_W + (JC + jl) * WP + k]     = Whrz[k * (2*H_) + H_ + jbase + jl];   // z
        sm[OFF_W + (2*JC + jl) * WP + k]   = Whn [k * H_ + jbase + jl];            // n
    }
    for (int idx = tid; idx < 3 * DIN * JC; idx += TPB) {
        int jl = idx & 63; int rem = idx >> 6;
        int g = rem / DIN, d = rem % DIN;
        sm[OFF_WI + (g * DIN + d) * JC + jl] = Wi[d * G3 + g * H_ + jbase + jl];
    }
    if (tid < 3 * JC) {
        int g = tid >> 6, jl = tid & 63;
        sm[OFF_BI + tid] = bi[g * H_ + jbase + jl];
    }
    if (tid < JC) sm[OFF_BN + tid] = bn[jbase + tid];
    for (int idx = tid; idx < BC * WP; idx += TPB) sm[OFF_H + idx] = 0.0f;  // h0 = 0
    if (tid < BC * DIN) {   // stage x for p = 0
        int bb = tid / DIN, d = tid % DIN;
        int gb = cbase + bb;
        sm[OFF_X + bb * 20 + d] = (d < D_) ? particles[gb * (P_ * D_) + d]
                                           : pw[gb * P_];
    }
    __syncthreads();
    CL_ARRIVE(); CL_WAIT();

    const int jl = tid >> 3, tg = tid & 7;
    const int wR = OFF_W + jl * WP;
    const int wZ = OFF_W + (JC + jl) * WP;
    const int wN = OFF_W + (2*JC + jl) * WP;
    const uint32_t smem_base = (uint32_t)__cvta_generic_to_shared(sm);

    const float bir = sm[OFF_BI + jl];
    const float biz = sm[OFF_BI + JC + jl];
    const float bin = sm[OFF_BI + 2*JC + jl];
    const float bnv = sm[OFF_BN + jl];

    for (int p = 0; p < P_; ++p) {
        const int cur = p & 1, nxt = cur ^ 1;

        // 1. prefetch x for step p+1 into registers (hidden under wait+k-loop)
        float xpre = 0.0f; int pb = 0, pd = 0;
        if (p + 1 < P_ && tid < BC * DIN) {
            pb = tid / DIN; pd = tid % DIN;
            int gb = cbase + pb;
            xpre = (pd < D_) ? particles[gb * (P_ * D_) + (p + 1) * D_ + pd]
                             : pw[gb * P_ + (p + 1)];
        }

        // 2. input-gate contributions: gi = x @ Wi + bi (no dependence on h)
        float gr = bir, gz = biz, gn = bin;
        const float* xc = &sm[OFF_X + (cur * BC + tg) * 20];
        #pragma unroll
        for (int d = 0; d < DIN; ++d) {
            float xv = xc[d];
            gr += xv * sm[OFF_WI + d * JC + jl];
            gz += xv * sm[OFF_WI + (DIN + d) * JC + jl];
            gn += xv * sm[OFF_WI + (2*DIN + d) * JC + jl];
        }

        // 3. wait for previous step's h scatter (overlapped with 1+2)
        if (p) CL_WAIT();

        // 4. recurrent dots over k with packed f32x2 FMA
        unsigned long long arA = 0, azA = 0, anA = 0;
        unsigned long long arB = 0, azB = 0, anB = 0;
        const int hoff = OFF_H + (cur * BC + tg) * WP;
        #pragma unroll 4
        for (int k = 0; k < H_; k += 4) {
            ulonglong2 vr = *reinterpret_cast<const ulonglong2*>(&sm[wR + k]);
            ulonglong2 vz = *reinterpret_cast<const ulonglong2*>(&sm[wZ + k]);
            ulonglong2 vn = *reinterpret_cast<const ulonglong2*>(&sm[wN + k]);
            ulonglong2 ha = *reinterpret_cast<const ulonglong2*>(&sm[hoff + k]);
            fma2(arA, ha.x, vr.x); fma2(arB, ha.y, vr.y);
            fma2(azA, ha.x, vz.x); fma2(azB, ha.y, vz.y);
            fma2(anA, ha.x, vn.x); fma2(anB, ha.y, vn.y);
        }

        // 5. gates / new hidden
        float r = sigf(gr + f2red(arA, arB));
        float z = sigf(gz + f2red(azA, azB));
        float n = tanh_f(gn + r * (f2red(anA, anB) + bnv));
        float hold = sm[hoff + jbase + jl];
        float hnew = n + z * (hold - n);

        // scatter owned element to all CTAs' next h buffer
        const int hdst = OFF_H + (nxt * BC + tg) * WP + jbase + jl;
        sm[hdst] = hnew;                                  // local
        uint32_t la = smem_base + (uint32_t)(hdst * 4);
        #pragma unroll
        for (int r2 = 0; r2 < CS; ++r2)
            if (r2 != rank) st_remote(la, (uint32_t)r2, hnew);

        // 6. stash prefetched x into next buffer (local)
        if (p + 1 < P_ && tid < BC * DIN)
            sm[OFF_X + (nxt * BC + pb) * 20 + pd] = xpre;

        // 7+8. order local stores for local readers, then release to cluster
        __syncthreads();
        CL_ARRIVE();
    }

    CL_WAIT();   // consume final arrives; h final lives in buffer 0

    g_enc[(cbase + tg) * H_ + jbase + jl] = sm[OFF_H + tg * WP + jbase + jl];
}

// =====================================================================
// Kernel 2: twin-critic MLP, BB=4 batch rows per block to amortize the
// weight stream 4x. grid (C, B/BB) = (2, 64), 256 threads (t = unit).
// =====================================================================
#define BB 4

__global__ void __launch_bounds__(256)
mlp_kernel(const float* __restrict__ actions,   // [B, A]
           const float* __restrict__ timev,     // [B]
           const float* __restrict__ W1,        // [C, INM, HID]
           const float* __restrict__ b1,        // [C, HID]
           const float* __restrict__ W2,        // [C, HID, HID]
           const float* __restrict__ b2,        // [C, HID]
           const float* __restrict__ W3,        // [C, HID, 1]
           const float* __restrict__ b3,        // [C, 1]
           const int*   __restrict__ nts,       // scalar
           float*       __restrict__ out)       // [B, C]
{
    __shared__ float hid[BB][INM];
    __shared__ float h1s[BB][HID_];
    __shared__ float red[BB][8];

    const int c = blockIdx.x, b0 = blockIdx.y * BB, t = threadIdx.x;
    const float tinv = 1.0f / (float)nts[0];

    for (int idx = t; idx < BB * INM; idx += 256) {
        int bb = idx / INM, i = idx - bb * INM;
        int b = b0 + bb;
        float v;
        if (i < H_)            v = g_enc[b * H_ + i];
        else if (i < H_ + ACT) v = actions[b * ACT + (i - H_)];
        else                   v = timev[b] * tinv;
        hid[bb][i] = v;
    }
    __syncthreads();

    // layer 1
    float bb1 = b1[c * HID_ + t];
    float a0 = bb1, a1 = bb1, a2 = bb1, a3 = bb1;
    const float* w1p = W1 + (size_t)c * INM * HID_ + t;
    #pragma unroll 5
    for (int i = 0; i < INM; ++i) {
        float w = w1p[(size_t)i * HID_];
        a0 += hid[0][i] * w; a1 += hid[1][i] * w;
        a2 += hid[2][i] * w; a3 += hid[3][i] * w;
    }
    h1s[0][t] = fmaxf(a0, 0.0f); h1s[1][t] = fmaxf(a1, 0.0f);
    h1s[2][t] = fmaxf(a2, 0.0f); h1s[3][t] = fmaxf(a3, 0.0f);
    __syncthreads();

    // layer 2
    float bb2 = b2[c * HID_ + t];
    a0 = bb2; a1 = bb2; a2 = bb2; a3 = bb2;
    const float* w2p = W2 + (size_t)c * HID_ * HID_ + t;
    #pragma unroll 8
    for (int i = 0; i < HID_; ++i) {
        float w = w2p[(size_t)i * HID_];
        a0 += h1s[0][i] * w; a1 += h1s[1][i] * w;
        a2 += h1s[2][i] * w; a3 += h1s[3][i] * w;
    }

    // layer 3 + reduction
    float w3v = W3[c * HID_ + t];
    float v0 = fmaxf(a0, 0.0f) * w3v;
    float v1 = fmaxf(a1, 0.0f) * w3v;
    float v2 = fmaxf(a2, 0.0f) * w3v;
    float v3 = fmaxf(a3, 0.0f) * w3v;
    #pragma unroll
    for (int o = 16; o > 0; o >>= 1) {
        v0 += __shfl_xor_sync(0xffffffffu, v0, o);
        v1 += __shfl_xor_sync(0xffffffffu, v1, o);
        v2 += __shfl_xor_sync(0xffffffffu, v2, o);
        v3 += __shfl_xor_sync(0xffffffffu, v3, o);
    }
    if ((t & 31) == 0) {
        int w = t >> 5;
        red[0][w] = v0; red[1][w] = v1; red[2][w] = v2; red[3][w] = v3;
    }
    __syncthreads();
    if (t < BB) {
        float s = b3[c];
        #pragma unroll
        for (int w = 0; w < 8; ++w) s += red[t][w];
        out[(b0 + t) * NCRIT + c] = s;
    }
}

// =====================================================================
extern "C" void kernel_launch(void* const* d_in, const int* in_sizes, int n_in,
                              void* d_out, int out_size)
{
    const float* particles = (const float*)d_in[0];
    const float* pw        = (const float*)d_in[1];
    const float* actions   = (const float*)d_in[2];
    const float* timev     = (const float*)d_in[3];
    const float* Wi        = (const float*)d_in[4];
    const float* bi        = (const float*)d_in[5];
    const float* Whrz      = (const float*)d_in[6];
    const float* Whn       = (const float*)d_in[7];
    const float* bn        = (const float*)d_in[8];
    const float* W1        = (const float*)d_in[9];
    const float* b1        = (const float*)d_in[10];
    const float* W2        = (const float*)d_in[11];
    const float* b2        = (const float*)d_in[12];
    const float* W3        = (const float*)d_in[13];
    const float* b3        = (const float*)d_in[14];
    const int*   nts       = (const int*)d_in[15];

    cudaFuncSetAttribute(gru_kernel,
                         cudaFuncAttributeMaxDynamicSharedMemorySize, SMEM_BYTES);

    gru_kernel<<<NCL * CS, TPB, SMEM_BYTES>>>(particles, pw, Wi, bi, Whrz, Whn, bn);

    dim3 g2(NCRIT, B_ / BB);
    mlp_kernel<<<g2, 256>>>(actions, timev, W1, b1, W2, b2, W3, b3, nts,
                            (float*)d_out);
}